// round 8
// baseline (speedup 1.0000x reference)
#include <cuda_runtime.h>
#include <stdint.h>

// Problem constants
#define BB 16
#define NN 4096
#define DD 256
#define KK 512
#define MM (BB * NN)            // 65536 positions
#define COMMIT_W 0.25f
#define MARGIN 1.25f            // > 2x worst-case tf32 screen error per distance pair

// Scratch (device globals: no allocation allowed)
__device__ float         g_esq[KK];
__device__ int           g_best[MM];
__device__ int           g_list[MM];
__device__ int           g_count;
__device__ double        g_loss;

// ---------------------------------------------------------------------------
// helpers
// ---------------------------------------------------------------------------
__device__ __forceinline__ float to_tf32(float x) {
    unsigned u;
    asm("cvt.rna.tf32.f32 %0, %1;" : "=r"(u) : "f"(x));
    return __uint_as_float(u);
}

__device__ __forceinline__ float4 to_tf32_v4(float4 v) {
    v.x = to_tf32(v.x); v.y = to_tf32(v.y);
    v.z = to_tf32(v.z); v.w = to_tf32(v.w);
    return v;
}

__device__ __forceinline__ void mma_tf32(float d[4], const unsigned a[4], const unsigned b[2]) {
    asm volatile(
        "mma.sync.aligned.m16n8k8.row.col.f32.tf32.tf32.f32 "
        "{%0,%1,%2,%3}, {%4,%5,%6,%7}, {%8,%9}, {%0,%1,%2,%3};\n"
        : "+f"(d[0]), "+f"(d[1]), "+f"(d[2]), "+f"(d[3])
        : "r"(a[0]), "r"(a[1]), "r"(a[2]), "r"(a[3]), "r"(b[0]), "r"(b[1]));
}

// ---------------------------------------------------------------------------
// Kernel 0: precompute ||e_k||^2 (fp32 exact); zero loss + compaction count.
// ---------------------------------------------------------------------------
__global__ void prep_kernel(const float* __restrict__ cb) {
    int k = blockIdx.x * blockDim.x + threadIdx.x;
    if (k == 0) { g_loss = 0.0; g_count = 0; }
    if (k < KK) {
        const float4* row = (const float4*)(cb + (size_t)k * DD);
        float s = 0.f;
#pragma unroll 16
        for (int i = 0; i < DD / 4; i++) {
            float4 v = row[i];
            s += v.x * v.x + v.y * v.y + v.z * v.z + v.w * v.w;
        }
        g_esq[k] = s;
    }
}

// ---------------------------------------------------------------------------
// Kernel 1: TF32 tensor-core screen with top-2 tracking (software-pipelined).
// CTA: 256 thr (8 warps, 4x2). CTA tile: 128 rows x 128 codes/pass, 4 passes.
// Double-buffered smem; LDG for chunk i+1 issued before the MMAs of chunk i;
// one __syncthreads per chunk. Numerics identical to the verified R6 screen.
// ---------------------------------------------------------------------------
__global__ void __launch_bounds__(256) screen_kernel(
    const float* __restrict__ z, const float* __restrict__ cb)
{
    __shared__ float zs[2][128][20];   // [buf][row][d]  (tf32-rounded)
    __shared__ float cs[2][128][20];   // [buf][code][d] (tf32-rounded)

    const int tid  = threadIdx.x;
    const int warp = tid >> 5;
    const int lane = tid & 31;
    const int wm   = warp >> 1;        // 0..3
    const int wn   = warp & 1;         // 0..1
    const int g    = lane >> 2;        // 0..7
    const int tig  = lane & 3;         // 0..3
    const int row0 = blockIdx.x * 128;

    // per-thread load slots: rows r and r+64, 4-float column group c4
    const int r  = tid >> 2;           // 0..63
    const int c4 = tid & 3;            // 0..3
    const float* zp0 = z + (size_t)(row0 + r) * DD + c4 * 4;
    const float* zp1 = zp0 + (size_t)64 * DD;

    // per-thread top-2 for 4 rows: e = mt*2 + h, row = wm*32 + mt*16 + g + 8h
    float v1[4], v2[4];
    int   i1[4];
#pragma unroll
    for (int e = 0; e < 4; e++) { v1[e] = 3.4e38f; v2[e] = 3.4e38f; i1[e] = 0; }

    for (int kc = 0; kc < KK / 128; kc++) {
        const float* cp0 = cb + (size_t)(kc * 128 + r) * DD + c4 * 4;
        const float* cp1 = cp0 + (size_t)64 * DD;

        float acc[2][8][4];
#pragma unroll
        for (int mt = 0; mt < 2; mt++)
#pragma unroll
            for (int nt = 0; nt < 8; nt++)
#pragma unroll
                for (int c = 0; c < 4; c++) acc[mt][nt][c] = 0.f;

        // ---- prologue: stage chunk 0 into buffer 0 ----
        {
            float4 a0 = *(const float4*)(zp0);
            float4 a1 = *(const float4*)(zp1);
            float4 b0 = *(const float4*)(cp0);
            float4 b1 = *(const float4*)(cp1);
            __syncthreads();   // buffers free (prev pass readers done)
            *(float4*)&zs[0][r     ][c4 * 4] = to_tf32_v4(a0);
            *(float4*)&zs[0][r + 64][c4 * 4] = to_tf32_v4(a1);
            *(float4*)&cs[0][r     ][c4 * 4] = to_tf32_v4(b0);
            *(float4*)&cs[0][r + 64][c4 * 4] = to_tf32_v4(b1);
        }
        __syncthreads();

#pragma unroll 2
        for (int it = 0; it < 16; it++) {
            const int cur = it & 1;
            // prefetch next chunk into registers (latency hides under MMAs)
            float4 a0, a1, b0, b1;
            if (it < 15) {
                const int dc = (it + 1) * 16;
                a0 = *(const float4*)(zp0 + dc);
                a1 = *(const float4*)(zp1 + dc);
                b0 = *(const float4*)(cp0 + dc);
                b1 = *(const float4*)(cp1 + dc);
            }

            // ---- MMAs on current buffer ----
#pragma unroll
            for (int q = 0; q < 2; q++) {
                const int q8 = q * 8;
                unsigned afr[2][4];
#pragma unroll
                for (int mt = 0; mt < 2; mt++) {
                    int rb = wm * 32 + mt * 16;
                    afr[mt][0] = __float_as_uint(zs[cur][rb + g    ][q8 + tig    ]);
                    afr[mt][1] = __float_as_uint(zs[cur][rb + g + 8][q8 + tig    ]);
                    afr[mt][2] = __float_as_uint(zs[cur][rb + g    ][q8 + tig + 4]);
                    afr[mt][3] = __float_as_uint(zs[cur][rb + g + 8][q8 + tig + 4]);
                }
                unsigned bfr[8][2];
#pragma unroll
                for (int nt = 0; nt < 8; nt++) {
                    int nb = wn * 64 + nt * 8 + g;
                    bfr[nt][0] = __float_as_uint(cs[cur][nb][q8 + tig    ]);
                    bfr[nt][1] = __float_as_uint(cs[cur][nb][q8 + tig + 4]);
                }
#pragma unroll
                for (int mt = 0; mt < 2; mt++)
#pragma unroll
                    for (int nt = 0; nt < 8; nt++)
                        mma_tf32(acc[mt][nt], afr[mt], bfr[nt]);
            }

            // ---- stage prefetched chunk into the other buffer ----
            if (it < 15) {
                const int nxt = cur ^ 1;
                *(float4*)&zs[nxt][r     ][c4 * 4] = to_tf32_v4(a0);
                *(float4*)&zs[nxt][r + 64][c4 * 4] = to_tf32_v4(a1);
                *(float4*)&cs[nxt][r     ][c4 * 4] = to_tf32_v4(b0);
                *(float4*)&cs[nxt][r + 64][c4 * 4] = to_tf32_v4(b1);
                __syncthreads();
            }
        }

        // fold this pass's 128 codes into top-2 (k ascending => first-hit ties)
#pragma unroll
        for (int nt = 0; nt < 8; nt++) {
#pragma unroll
            for (int c = 0; c < 4; c++) {
                int k = kc * 128 + wn * 64 + nt * 8 + 2 * tig + (c & 1);
                float es = g_esq[k];
#pragma unroll
                for (int mt = 0; mt < 2; mt++) {
                    int e = mt * 2 + (c >> 1);
                    float dist = fmaf(-2.f, acc[mt][nt][c], es);
                    if (dist < v1[e]) { v2[e] = v1[e]; v1[e] = dist; i1[e] = k; }
                    else if (dist < v2[e]) { v2[e] = dist; }
                }
            }
        }
    }

    // cross-thread reduction: 8 threads per row (slot = wn*4 + tig).
    // Reduction arrays alias the (now dead) tile buffers.
    __syncthreads();
    float* rv1 = (float*)zs;           // 128*8 floats
    float* rv2 = rv1 + 1024;           // 128*8 floats
    int*   ri1 = (int*)(rv2 + 1024);   // 128*8 ints
    const int slot = wn * 4 + tig;
#pragma unroll
    for (int e = 0; e < 4; e++) {
        int rr = wm * 32 + (e >> 1) * 16 + g + 8 * (e & 1);
        rv1[rr * 8 + slot] = v1[e];
        ri1[rr * 8 + slot] = i1[e];
        rv2[rr * 8 + slot] = v2[e];
    }
    __syncthreads();
    if (tid < 128) {
        float V1 = rv1[tid * 8], V2 = rv2[tid * 8];
        int   I1 = ri1[tid * 8];
#pragma unroll
        for (int s = 1; s < 8; s++) {
            float a = rv1[tid * 8 + s], b = rv2[tid * 8 + s];
            int  ia = ri1[tid * 8 + s];
            if (a < V1)       { V2 = fminf(V1, b); V1 = a; I1 = ia; }
            else if (a == V1) { if (ia < I1) I1 = ia; V2 = V1; }   // tie -> rescore
            else              { V2 = fminf(V2, a); }
        }
        g_best[row0 + tid] = I1;
        if (V2 - V1 <= MARGIN) {
            int p = atomicAdd(&g_count, 1);
            g_list[p] = row0 + tid;
        }
    }
}

// ---------------------------------------------------------------------------
// Kernel 2: exact fp32 rescore of compacted flagged rows, tiled GEMM-argmin.
// ---------------------------------------------------------------------------
__global__ void __launch_bounds__(256, 2) rescore_kernel(
    const float* __restrict__ z, const float* __restrict__ cb)
{
    const int cnt = g_count;
    if (blockIdx.x * 64 >= cnt) return;

    __shared__ int   rowid[64];
    __shared__ float zs[64][64];   // [d][m]
    __shared__ float cs[64][64];   // [d][k]
    __shared__ float redv[64][17];
    __shared__ int   redi[64][17];

    const int tid = threadIdx.x;
    const int tm  = tid & 15;
    const int tk  = tid >> 4;

    if (tid < 64) {
        int i = blockIdx.x * 64 + tid;
        rowid[tid] = g_list[i < cnt ? i : cnt - 1];
    }
    __syncthreads();

    const int lm = tid & 63;
    const int lq = tid >> 6;       // 0..3
    const int myrow = rowid[lm];

    float bestv[4];
    int   besti[4];
#pragma unroll
    for (int i = 0; i < 4; i++) { bestv[i] = 3.4e38f; besti[i] = 0; }

    for (int kc = 0; kc < KK; kc += 64) {
        float acc[4][4];
#pragma unroll
        for (int i = 0; i < 4; i++)
#pragma unroll
            for (int j = 0; j < 4; j++) acc[i][j] = 0.f;

        for (int dc = 0; dc < DD; dc += 64) {
            __syncthreads();
            {
                const float4* zp = (const float4*)(z + (size_t)myrow * DD + dc + lq * 16);
#pragma unroll
                for (int i = 0; i < 4; i++) {
                    float4 v = zp[i];
                    int d = lq * 16 + i * 4;
                    zs[d + 0][lm] = v.x; zs[d + 1][lm] = v.y;
                    zs[d + 2][lm] = v.z; zs[d + 3][lm] = v.w;
                }
            }
            {
                const float4* cp = (const float4*)(cb + (size_t)(kc + lm) * DD + dc + lq * 16);
#pragma unroll
                for (int i = 0; i < 4; i++) {
                    float4 v = cp[i];
                    int d = lq * 16 + i * 4;
                    cs[d + 0][lm] = v.x; cs[d + 1][lm] = v.y;
                    cs[d + 2][lm] = v.z; cs[d + 3][lm] = v.w;
                }
            }
            __syncthreads();

#pragma unroll 16
            for (int d = 0; d < 64; d++) {
                float4 za = *(const float4*)&zs[d][tm * 4];
                float4 ca = *(const float4*)&cs[d][tk * 4];
                float zr[4] = { za.x, za.y, za.z, za.w };
                float cr[4] = { ca.x, ca.y, ca.z, ca.w };
#pragma unroll
                for (int i = 0; i < 4; i++)
#pragma unroll
                    for (int j = 0; j < 4; j++)
                        acc[i][j] += zr[i] * cr[j];
            }
        }

#pragma unroll
        for (int j = 0; j < 4; j++) {
            int kidx = kc + tk * 4 + j;
            float es = g_esq[kidx];
#pragma unroll
            for (int i = 0; i < 4; i++) {
                float dist = fmaf(-2.f, acc[i][j], es);
                if (dist < bestv[i]) { bestv[i] = dist; besti[i] = kidx; }
            }
        }
    }

    __syncthreads();
#pragma unroll
    for (int i = 0; i < 4; i++) {
        redv[tm * 4 + i][tk] = bestv[i];
        redi[tm * 4 + i][tk] = besti[i];
    }
    __syncthreads();
    if (tid < 64) {
        float bv = redv[tid][0];
        int   bi = redi[tid][0];
#pragma unroll
        for (int t = 1; t < 16; t++) {
            float v = redv[tid][t];
            int   ix = redi[tid][t];
            if (v < bv || (v == bv && ix < bi)) { bv = v; bi = ix; }
        }
        g_best[rowid[tid]] = bi;
    }
}

// ---------------------------------------------------------------------------
// Kernel 3: gather + mask + loss accumulation. One warp per position.
// ---------------------------------------------------------------------------
__global__ void __launch_bounds__(256) quant_kernel(
    const float* __restrict__ z, const unsigned int* __restrict__ mask,
    const float* __restrict__ cb, float* __restrict__ outq,
    float* __restrict__ outi)
{
    __shared__ float wsum[8];
    const int warp = threadIdx.x >> 5;
    const int lane = threadIdx.x & 31;
    const int pos  = blockIdx.x * 8 + warp;

    const int idx = g_best[pos];
    const bool mk = (mask[pos] != 0u);
    const float m = mk ? 1.f : 0.f;
    const float4* zp = (const float4*)(z  + (size_t)pos * DD);
    const float4* ep = (const float4*)(cb + (size_t)idx * DD);
    float4* op = (float4*)(outq + (size_t)pos * DD);

    float s = 0.f;
#pragma unroll
    for (int i = lane; i < DD / 4; i += 32) {
        float4 zv = zp[i];
        float4 ev = ep[i];
        float dx = ev.x - zv.x, dy = ev.y - zv.y,
              dz = ev.z - zv.z, dw = ev.w - zv.w;
        s += dx * dx + dy * dy + dz * dz + dw * dw;
        op[i] = make_float4(ev.x * m, ev.y * m, ev.z * m, ev.w * m);
    }
    if (lane == 0) outi[pos] = mk ? (float)idx : -1.0f;

#pragma unroll
    for (int off = 16; off > 0; off >>= 1)
        s += __shfl_down_sync(0xFFFFFFFFu, s, off);
    if (lane == 0) wsum[warp] = s;
    __syncthreads();
    if (threadIdx.x == 0) {
        float b = 0.f;
#pragma unroll
        for (int w = 0; w < 8; w++) b += wsum[w];
        atomicAdd(&g_loss, (double)b);
    }
}

// ---------------------------------------------------------------------------
// Kernel 4: finalize commit loss.
// ---------------------------------------------------------------------------
__global__ void finalize_kernel(float* __restrict__ out_loss) {
    out_loss[0] = (float)(COMMIT_W * g_loss / ((double)MM * (double)DD));
}

// ---------------------------------------------------------------------------
extern "C" void kernel_launch(void* const* d_in, const int* in_sizes, int n_in,
                              void* d_out, int out_size) {
    const float*        z    = (const float*)d_in[0];
    const unsigned int* mask = (const unsigned int*)d_in[1];
    const float*        cb   = (const float*)d_in[2];

    float* outq = (float*)d_out;                         // (B,N,D)
    float* outi = outq + (size_t)MM * DD;                // (B,N) indices as float
    float* outl = outi + MM;                             // scalar loss

    prep_kernel<<<4, 128>>>(cb);
    screen_kernel<<<MM / 128, 256>>>(z, cb);
    rescore_kernel<<<MM / 64, 256>>>(z, cb);
    quant_kernel<<<MM / 8, 256>>>(z, mask, cb, outq, outi);
    finalize_kernel<<<1, 1>>>(outl);
}

// round 11
// speedup vs baseline: 1.2074x; 1.2074x over previous
#include <cuda_runtime.h>
#include <cuda_fp16.h>
#include <stdint.h>

// Problem constants
#define BB 16
#define NN 4096
#define DD 256
#define KK 512
#define MM (BB * NN)            // 65536 positions
#define COMMIT_W 0.25f
#define MARGIN 1.25f            // > 2x worst-case fp16/tf32 screen error per distance pair

// Scratch (device globals: no allocation allowed)
__device__ float         g_esq[KK];
__device__ int           g_best[MM];
__device__ int           g_list[MM];
__device__ int           g_count;
__device__ double        g_loss;

// ---------------------------------------------------------------------------
// helpers
// ---------------------------------------------------------------------------
__device__ __forceinline__ uint32_t f2h2(float a, float b) {
    __half2 h = __floats2half2_rn(a, b);
    return *(uint32_t*)&h;
}

// fp16 MMA m16n8k16, fp32 accumulate (supported on base sm_103 target)
__device__ __forceinline__ void mma_f16(float d[4], const uint32_t a[4], const uint32_t b[2]) {
    asm volatile(
        "mma.sync.aligned.m16n8k16.row.col.f32.f16.f16.f32 "
        "{%0,%1,%2,%3}, {%4,%5,%6,%7}, {%8,%9}, {%0,%1,%2,%3};\n"
        : "+f"(d[0]), "+f"(d[1]), "+f"(d[2]), "+f"(d[3])
        : "r"(a[0]), "r"(a[1]), "r"(a[2]), "r"(a[3]), "r"(b[0]), "r"(b[1]));
}

// ---------------------------------------------------------------------------
// Kernel 0: precompute ||e_k||^2 (fp32 exact); zero loss + compaction count.
// ---------------------------------------------------------------------------
__global__ void prep_kernel(const float* __restrict__ cb) {
    int k = blockIdx.x * blockDim.x + threadIdx.x;
    if (k == 0) { g_loss = 0.0; g_count = 0; }
    if (k < KK) {
        const float4* row = (const float4*)(cb + (size_t)k * DD);
        float s = 0.f;
#pragma unroll 16
        for (int i = 0; i < DD / 4; i++) {
            float4 v = row[i];
            s += v.x * v.x + v.y * v.y + v.z * v.z + v.w * v.w;
        }
        g_esq[k] = s;
    }
}

// ---------------------------------------------------------------------------
// Kernel 1: FP16 tensor-core screen with top-2 tracking.
// CTA: 256 thr (8 warps, 4x2 grid). CTA tile: 128 rows x 128 codes per pass,
// 4 passes cover K=512. Warp tile 32x64: per 16-d chunk, 2 m16 x 8 n8 = 16
// m16n8k16 MMAs (half the instructions + half the LDS of the tf32 version at
// the same 11-bit input precision -> identical flagged set & final indices).
// Smem rows stride 24 halves: fragment half2 loads hit all 32 banks.
// ---------------------------------------------------------------------------
__global__ void __launch_bounds__(256, 2) screen_kernel(
    const float* __restrict__ z, const float* __restrict__ cb)
{
    __shared__ __half zs[128][24];   // [row][d-chunk]  (rn-rounded)
    __shared__ __half cs[128][24];   // [code][d-chunk] (rn-rounded)
    __shared__ float rv1[128][8];
    __shared__ float rv2[128][8];
    __shared__ int   ri1[128][8];

    const int tid  = threadIdx.x;
    const int warp = tid >> 5;
    const int lane = tid & 31;
    const int wm   = warp >> 1;        // 0..3
    const int wn   = warp & 1;         // 0..1
    const int g    = lane >> 2;        // 0..7
    const int tig  = lane & 3;         // 0..3
    const int row0 = blockIdx.x * 128;

    // tile-load mapping: each thread loads 8 floats (half a row) per tile
    const int lr = tid >> 1;           // 0..127
    const int sg = (tid & 1) * 8;      // float offset 0 or 8 within 16-d chunk

    // per-thread top-2 for 4 rows: e = mt*2 + h, row = wm*32 + mt*16 + g + 8h
    float v1[4], v2[4];
    int   i1[4];
#pragma unroll
    for (int e = 0; e < 4; e++) { v1[e] = 3.4e38f; v2[e] = 3.4e38f; i1[e] = 0; }

    for (int kc = 0; kc < KK / 128; kc++) {
        float acc[2][8][4];
#pragma unroll
        for (int mt = 0; mt < 2; mt++)
#pragma unroll
            for (int nt = 0; nt < 8; nt++)
#pragma unroll
                for (int c = 0; c < 4; c++) acc[mt][nt][c] = 0.f;

        for (int dc = 0; dc < DD; dc += 16) {
            __syncthreads();   // protect smem from previous iteration's readers
            // stage z chunk [128 x 16] as half
            {
                const float4* p = (const float4*)(z + (size_t)(row0 + lr) * DD + dc + sg);
                float4 u = p[0], v = p[1];
                *(uint4*)&zs[lr][sg] = make_uint4(
                    f2h2(u.x, u.y), f2h2(u.z, u.w), f2h2(v.x, v.y), f2h2(v.z, v.w));
            }
            // stage codebook chunk [128 x 16] as half
            {
                const float4* p = (const float4*)(cb + (size_t)(kc * 128 + lr) * DD + dc + sg);
                float4 u = p[0], v = p[1];
                *(uint4*)&cs[lr][sg] = make_uint4(
                    f2h2(u.x, u.y), f2h2(u.z, u.w), f2h2(v.x, v.y), f2h2(v.z, v.w));
            }
            __syncthreads();

            // fragments: A row-major m16k16, B k-major n8k16
            uint32_t afr[2][4];
#pragma unroll
            for (int mt = 0; mt < 2; mt++) {
                int rb = wm * 32 + mt * 16;
                afr[mt][0] = *(const uint32_t*)&zs[rb + g    ][2 * tig    ];
                afr[mt][1] = *(const uint32_t*)&zs[rb + g + 8][2 * tig    ];
                afr[mt][2] = *(const uint32_t*)&zs[rb + g    ][2 * tig + 8];
                afr[mt][3] = *(const uint32_t*)&zs[rb + g + 8][2 * tig + 8];
            }
            uint32_t bfr[8][2];
#pragma unroll
            for (int nt = 0; nt < 8; nt++) {
                int nb = wn * 64 + nt * 8 + g;
                bfr[nt][0] = *(const uint32_t*)&cs[nb][2 * tig    ];
                bfr[nt][1] = *(const uint32_t*)&cs[nb][2 * tig + 8];
            }
#pragma unroll
            for (int mt = 0; mt < 2; mt++)
#pragma unroll
                for (int nt = 0; nt < 8; nt++)
                    mma_f16(acc[mt][nt], afr[mt], bfr[nt]);
        }

        // fold this pass's 128 codes into top-2 (k ascending => first-hit ties)
#pragma unroll
        for (int nt = 0; nt < 8; nt++) {
#pragma unroll
            for (int c = 0; c < 4; c++) {
                int k = kc * 128 + wn * 64 + nt * 8 + 2 * tig + (c & 1);
                float es = g_esq[k];
#pragma unroll
                for (int mt = 0; mt < 2; mt++) {
                    int e = mt * 2 + (c >> 1);
                    float dist = fmaf(-2.f, acc[mt][nt][c], es);
                    if (dist < v1[e]) { v2[e] = v1[e]; v1[e] = dist; i1[e] = k; }
                    else if (dist < v2[e]) { v2[e] = dist; }
                }
            }
        }
    }

    // cross-thread reduction: 8 threads per row (slot = wn*4 + tig)
    __syncthreads();
    const int slot = wn * 4 + tig;
#pragma unroll
    for (int e = 0; e < 4; e++) {
        int r = wm * 32 + (e >> 1) * 16 + g + 8 * (e & 1);
        rv1[r][slot] = v1[e];
        ri1[r][slot] = i1[e];
        rv2[r][slot] = v2[e];
    }
    __syncthreads();
    if (tid < 128) {
        float V1 = rv1[tid][0], V2 = rv2[tid][0];
        int   I1 = ri1[tid][0];
#pragma unroll
        for (int s = 1; s < 8; s++) {
            float a = rv1[tid][s], b = rv2[tid][s];
            int  ia = ri1[tid][s];
            if (a < V1)       { V2 = fminf(V1, b); V1 = a; I1 = ia; }
            else if (a == V1) { if (ia < I1) I1 = ia; V2 = V1; }   // tie -> rescore
            else              { V2 = fminf(V2, a); }
        }
        g_best[row0 + tid] = I1;
        if (V2 - V1 <= MARGIN) {
            int p = atomicAdd(&g_count, 1);
            g_list[p] = row0 + tid;
        }
    }
}

// ---------------------------------------------------------------------------
// Kernel 2: exact fp32 rescore of compacted flagged rows, tiled GEMM-argmin.
// ---------------------------------------------------------------------------
__global__ void __launch_bounds__(256, 2) rescore_kernel(
    const float* __restrict__ z, const float* __restrict__ cb)
{
    const int cnt = g_count;
    if (blockIdx.x * 64 >= cnt) return;

    __shared__ int   rowid[64];
    __shared__ float zs[64][64];   // [d][m]
    __shared__ float cs[64][64];   // [d][k]
    __shared__ float redv[64][17];
    __shared__ int   redi[64][17];

    const int tid = threadIdx.x;
    const int tm  = tid & 15;
    const int tk  = tid >> 4;

    if (tid < 64) {
        int i = blockIdx.x * 64 + tid;
        rowid[tid] = g_list[i < cnt ? i : cnt - 1];
    }
    __syncthreads();

    const int lm = tid & 63;
    const int lq = tid >> 6;       // 0..3
    const int myrow = rowid[lm];

    float bestv[4];
    int   besti[4];
#pragma unroll
    for (int i = 0; i < 4; i++) { bestv[i] = 3.4e38f; besti[i] = 0; }

    for (int kc = 0; kc < KK; kc += 64) {
        float acc[4][4];
#pragma unroll
        for (int i = 0; i < 4; i++)
#pragma unroll
            for (int j = 0; j < 4; j++) acc[i][j] = 0.f;

        for (int dc = 0; dc < DD; dc += 64) {
            __syncthreads();
            {
                const float4* zp = (const float4*)(z + (size_t)myrow * DD + dc + lq * 16);
#pragma unroll
                for (int i = 0; i < 4; i++) {
                    float4 v = zp[i];
                    int d = lq * 16 + i * 4;
                    zs[d + 0][lm] = v.x; zs[d + 1][lm] = v.y;
                    zs[d + 2][lm] = v.z; zs[d + 3][lm] = v.w;
                }
            }
            {
                const float4* cp = (const float4*)(cb + (size_t)(kc + lm) * DD + dc + lq * 16);
#pragma unroll
                for (int i = 0; i < 4; i++) {
                    float4 v = cp[i];
                    int d = lq * 16 + i * 4;
                    cs[d + 0][lm] = v.x; cs[d + 1][lm] = v.y;
                    cs[d + 2][lm] = v.z; cs[d + 3][lm] = v.w;
                }
            }
            __syncthreads();

#pragma unroll 16
            for (int d = 0; d < 64; d++) {
                float4 za = *(const float4*)&zs[d][tm * 4];
                float4 ca = *(const float4*)&cs[d][tk * 4];
                float zr[4] = { za.x, za.y, za.z, za.w };
                float cr[4] = { ca.x, ca.y, ca.z, ca.w };
#pragma unroll
                for (int i = 0; i < 4; i++)
#pragma unroll
                    for (int j = 0; j < 4; j++)
                        acc[i][j] += zr[i] * cr[j];
            }
        }

#pragma unroll
        for (int j = 0; j < 4; j++) {
            int kidx = kc + tk * 4 + j;
            float es = g_esq[kidx];
#pragma unroll
            for (int i = 0; i < 4; i++) {
                float dist = fmaf(-2.f, acc[i][j], es);
                if (dist < bestv[i]) { bestv[i] = dist; besti[i] = kidx; }
            }
        }
    }

    __syncthreads();
#pragma unroll
    for (int i = 0; i < 4; i++) {
        redv[tm * 4 + i][tk] = bestv[i];
        redi[tm * 4 + i][tk] = besti[i];
    }
    __syncthreads();
    if (tid < 64) {
        float bv = redv[tid][0];
        int   bi = redi[tid][0];
#pragma unroll
        for (int t = 1; t < 16; t++) {
            float v = redv[tid][t];
            int   ix = redi[tid][t];
            if (v < bv || (v == bv && ix < bi)) { bv = v; bi = ix; }
        }
        g_best[rowid[tid]] = bi;
    }
}

// ---------------------------------------------------------------------------
// Kernel 3: gather + mask + loss accumulation. One warp per position.
// Mask read as 32-bit words (nonzero == true): works for int32 or float32.
// ---------------------------------------------------------------------------
__global__ void __launch_bounds__(256) quant_kernel(
    const float* __restrict__ z, const unsigned int* __restrict__ mask,
    const float* __restrict__ cb, float* __restrict__ outq,
    float* __restrict__ outi)
{
    __shared__ float wsum[8];
    const int warp = threadIdx.x >> 5;
    const int lane = threadIdx.x & 31;
    const int pos  = blockIdx.x * 8 + warp;

    const int idx = g_best[pos];
    const bool mk = (mask[pos] != 0u);
    const float m = mk ? 1.f : 0.f;
    const float4* zp = (const float4*)(z  + (size_t)pos * DD);
    const float4* ep = (const float4*)(cb + (size_t)idx * DD);
    float4* op = (float4*)(outq + (size_t)pos * DD);

    float s = 0.f;
#pragma unroll
    for (int i = lane; i < DD / 4; i += 32) {
        float4 zv = zp[i];
        float4 ev = ep[i];
        float dx = ev.x - zv.x, dy = ev.y - zv.y,
              dz = ev.z - zv.z, dw = ev.w - zv.w;
        s += dx * dx + dy * dy + dz * dz + dw * dw;
        op[i] = make_float4(ev.x * m, ev.y * m, ev.z * m, ev.w * m);
    }
    if (lane == 0) outi[pos] = mk ? (float)idx : -1.0f;

#pragma unroll
    for (int off = 16; off > 0; off >>= 1)
        s += __shfl_down_sync(0xFFFFFFFFu, s, off);
    if (lane == 0) wsum[warp] = s;
    __syncthreads();
    if (threadIdx.x == 0) {
        float b = 0.f;
#pragma unroll
        for (int w = 0; w < 8; w++) b += wsum[w];
        atomicAdd(&g_loss, (double)b);
    }
}

// ---------------------------------------------------------------------------
// Kernel 4: finalize commit loss.
// ---------------------------------------------------------------------------
__global__ void finalize_kernel(float* __restrict__ out_loss) {
    out_loss[0] = (float)(COMMIT_W * g_loss / ((double)MM * (double)DD));
}

// ---------------------------------------------------------------------------
extern "C" void kernel_launch(void* const* d_in, const int* in_sizes, int n_in,
                              void* d_out, int out_size) {
    const float*        z    = (const float*)d_in[0];
    const unsigned int* mask = (const unsigned int*)d_in[1];
    const float*        cb   = (const float*)d_in[2];

    float* outq = (float*)d_out;                         // (B,N,D)
    float* outi = outq + (size_t)MM * DD;                // (B,N) indices as float
    float* outl = outi + MM;                             // scalar loss

    prep_kernel<<<4, 128>>>(cb);
    screen_kernel<<<MM / 128, 256>>>(z, cb);
    rescore_kernel<<<MM / 64, 256>>>(z, cb);
    quant_kernel<<<MM / 8, 256>>>(z, mask, cb, outq, outi);
    finalize_kernel<<<1, 1>>>(outl);
}